// round 1
// baseline (speedup 1.0000x reference)
#include <cuda_runtime.h>
#include <cuda_fp16.h>

// Sinkhorn: B=8, m=n=1024, lambda=10, max_distance=5, 100 iterations,
// uniform marginals r=c=1/1024.
//
// Persistent-kernel design:
//   grid = 8 batches x 16 blocks, 256 threads/block, 1 block/SM (co-resident).
//   Each block owns 64 rows of K for its batch, stored in SMEM as fp16*32.
//   Iteration:
//     phaseA: partial w_g[j] = sum_{i in my rows} K[i][j]*u[i]  -> g_wp (stcg)
//     barrier(batch)
//     reduce: block g reduces columns [64g,64g+64) over 16 partials -> v -> g_v
//     barrier(batch)
//     load v, phaseB: t[i] = dot(K[i,:], v); u[i] = r/t[i] (block-local)
//   Final: v after 100 u-updates, then P = u * exp(-10*min(M,5)) (fp32) * v.
// Deterministic: no fp atomics; fixed reduction order.

#define BB    8
#define NN    1024
#define GG    16
#define RPB   64          // rows per block (1024/16)
#define NT    256
#define ITERS 100
#define RINV  (1.0f/1024.0f)
#define KSCALE 32.0f      // keep fp16 K values in normal range

#define SMEM_BYTES (RPB*NN*2 + NN*4 + RPB*4)   // Ks + v_s + u_s = 135424

__device__ float    g_wp[BB][GG][NN];   // per-block partial w
__device__ float    g_v[BB][NN];        // reduced v (scaled: v_true/KSCALE)
__device__ unsigned g_bar[BB];          // per-batch barrier counters

__global__ void zero_bar_kernel() {
    if (threadIdx.x < BB) g_bar[threadIdx.x] = 0u;
}

// Per-batch grid barrier: monotonic counter, target = phase*GG.
__device__ __forceinline__ void barrier_batch(unsigned* ctr, unsigned target) {
    __threadfence();            // make my stcg stores globally visible
    __syncthreads();
    if (threadIdx.x == 0) {
        atomicAdd(ctr, 1u);
        volatile unsigned* vc = ctr;    // ld.volatile.global -> bypasses L1
        while (*vc < target) { }
        __threadfence();
    }
    __syncthreads();
}

__global__ void __launch_bounds__(NT, 1)
sinkhorn_persistent(const float* __restrict__ Min, float* __restrict__ out)
{
    extern __shared__ unsigned char smraw[];
    __half2* Ks  = reinterpret_cast<__half2*>(smraw);           // [RPB][NN/2]
    float*   v_s = reinterpret_cast<float*>(smraw + RPB*NN*2);  // [NN]
    float*   u_s = v_s + NN;                                    // [RPB]

    const int bid  = blockIdx.x;
    const int b    = bid >> 4;
    const int g    = bid & (GG - 1);
    const int t    = threadIdx.x;
    const int lane = t & 31;
    const int wrp  = t >> 5;

    const size_t base = ((size_t)b * NN + (size_t)g * RPB) * NN;
    const float* Mb   = Min + base;
    float*       outb = out + base;

    // ---- Build scaled fp16 K tile in SMEM ----
    for (int idx = t; idx < RPB * NN / 2; idx += NT) {
        float2 m2 = reinterpret_cast<const float2*>(Mb)[idx];
        float k0 = KSCALE * __expf(-10.0f * fminf(m2.x, 5.0f));
        float k1 = KSCALE * __expf(-10.0f * fminf(m2.y, 5.0f));
        Ks[idx] = __floats2half2_rn(k0, k1);
    }
    if (t < RPB) u_s[t] = RINV;
    __syncthreads();

    unsigned* ctr = &g_bar[b];
    unsigned phase = 0;

    for (int it = 0; it <= ITERS; ++it) {
        // ---- Phase A: partial w over my 64 rows; thread t owns cols [4t,4t+4) ----
        float a0 = 0.f, a1 = 0.f, a2 = 0.f, a3 = 0.f;
        {
            const uint2* rowv;
            #pragma unroll 4
            for (int r = 0; r < RPB; ++r) {
                float ur = u_s[r];
                rowv = reinterpret_cast<const uint2*>(Ks + (size_t)r * (NN / 2));
                uint2 pk = rowv[t];
                __half2 h0 = *reinterpret_cast<__half2*>(&pk.x);
                __half2 h1 = *reinterpret_cast<__half2*>(&pk.y);
                float2 f0 = __half22float2(h0);
                float2 f1 = __half22float2(h1);
                a0 = fmaf(f0.x, ur, a0);
                a1 = fmaf(f0.y, ur, a1);
                a2 = fmaf(f1.x, ur, a2);
                a3 = fmaf(f1.y, ur, a3);
            }
        }
        __stcg(reinterpret_cast<float4*>(&g_wp[b][g][4 * t]),
               make_float4(a0, a1, a2, a3));

        barrier_batch(ctr, (++phase) * GG);

        // ---- Reduce my 64-column slice across the 16 partials -> v ----
        if (t < RPB) {
            int col = g * RPB + t;
            float s = 0.f;
            #pragma unroll
            for (int p = 0; p < GG; ++p) s += __ldcg(&g_wp[b][p][col]);
            __stcg(&g_v[b][col], RINV / s);   // = v_true[col] / KSCALE
        }

        barrier_batch(ctr, (++phase) * GG);

        for (int idx = t; idx < NN; idx += NT) v_s[idx] = __ldcg(&g_v[b][idx]);
        __syncthreads();

        if (it < ITERS) {
            // ---- Phase B: warp wrp handles rows [8*wrp, 8*wrp+8) ----
            float2 vv[16];
            #pragma unroll
            for (int q = 0; q < 16; ++q)
                vv[q] = reinterpret_cast<const float2*>(v_s)[lane + 32 * q];

            #pragma unroll
            for (int k = 0; k < 8; ++k) {
                int r = wrp * 8 + k;
                float s = 0.f;
                #pragma unroll
                for (int q = 0; q < 16; ++q) {
                    __half2 h = Ks[(size_t)r * (NN / 2) + lane + 32 * q];
                    float2 f = __half22float2(h);
                    s = fmaf(f.x, vv[q].x, s);
                    s = fmaf(f.y, vv[q].y, s);
                }
                #pragma unroll
                for (int off = 16; off > 0; off >>= 1)
                    s += __shfl_xor_sync(0xffffffffu, s, off);
                if (lane == 0) u_s[r] = RINV / s;   // (K*KSCALE)@(v/KSCALE) = K@v
            }
            __syncthreads();
        }
    }

    // ---- Epilogue: P[i][j] = u[i] * exp(-10*min(M,5)) * v[j], fp32 K ----
    for (int r = 0; r < RPB; ++r) {
        float ur = u_s[r];
        float4 m4 = reinterpret_cast<const float4*>(Mb + (size_t)r * NN)[t];
        float v0 = KSCALE * v_s[4 * t + 0];
        float v1 = KSCALE * v_s[4 * t + 1];
        float v2 = KSCALE * v_s[4 * t + 2];
        float v3 = KSCALE * v_s[4 * t + 3];
        float4 o;
        o.x = ur * __expf(-10.0f * fminf(m4.x, 5.0f)) * v0;
        o.y = ur * __expf(-10.0f * fminf(m4.y, 5.0f)) * v1;
        o.z = ur * __expf(-10.0f * fminf(m4.z, 5.0f)) * v2;
        o.w = ur * __expf(-10.0f * fminf(m4.w, 5.0f)) * v3;
        reinterpret_cast<float4*>(outb + (size_t)r * NN)[t] = o;
    }
}

extern "C" void kernel_launch(void* const* d_in, const int* in_sizes, int n_in,
                              void* d_out, int out_size) {
    (void)in_sizes; (void)n_in; (void)out_size;
    const float* M = (const float*)d_in[0];
    float* out = (float*)d_out;

    cudaFuncSetAttribute(sinkhorn_persistent,
                         cudaFuncAttributeMaxDynamicSharedMemorySize, SMEM_BYTES);

    zero_bar_kernel<<<1, 32>>>();
    sinkhorn_persistent<<<BB * GG, NT, SMEM_BYTES>>>(M, out);
}

// round 10
// speedup vs baseline: 1.7071x; 1.7071x over previous
#include <cuda_runtime.h>
#include <cuda_fp16.h>

// Sinkhorn (B=8, 1024x1024, lambda=10, 100 iters, uniform marginals).
// Persistent kernel: 8 batches x 16 blocks, 512 threads, 1 block/SM,
// K tile (64 rows, fp16*32) resident in SMEM.
// ONE global (per-batch) barrier per iteration:
//   phaseA: partial w contribution for my 64 rows -> fp16 partial to L2
//   barrier(batch)
//   every block reduces all 16 partials itself -> full v in SMEM
//   phaseB: u[i] = r / dot(K[i,:], v)   (block-local rows)
// Final P = u * exp(-10*min(M,5)) (fp32) * v. Deterministic reduction order.

#define BB    8
#define NN    1024
#define NH    (NN/2)
#define GG    16
#define RPB   64
#define NT    512
#define ITERS 100
#define RINV  (1.0f/1024.0f)
#define KSCALE 32.0f

#define SMEM_BYTES (RPB*NN*2 + NN*4 + RPB*4)   // Ks + v_s + u_s = 135424

__device__ __half2  g_wp[2][BB][GG][NH];   // double-buffered fp16 partials
__device__ unsigned g_bar[BB][32];         // one 128B line per batch

__global__ void zero_bar_kernel() {
    if (threadIdx.x < BB) g_bar[threadIdx.x][0] = 0u;
}

static __device__ __forceinline__ unsigned ld_acq(const unsigned* p) {
    unsigned v;
    asm volatile("ld.acquire.gpu.global.u32 %0, [%1];" : "=r"(v) : "l"(p) : "memory");
    return v;
}
static __device__ __forceinline__ void red_rel_add1(unsigned* p) {
    asm volatile("red.release.gpu.global.add.u32 [%0], 1;" :: "l"(p) : "memory");
}

__global__ void __launch_bounds__(NT, 1)
sinkhorn_persistent(const float* __restrict__ Min, float* __restrict__ out)
{
    extern __shared__ unsigned char smraw[];
    __half2* Ks  = reinterpret_cast<__half2*>(smraw);            // [RPB][NH]
    float*   v_s = reinterpret_cast<float*>(smraw + RPB*NN*2);   // [NN]
    float*   u_s = v_s + NN;                                     // [RPB]

    const int bid  = blockIdx.x;
    const int b    = bid >> 4;
    const int g    = bid & (GG - 1);
    const int t    = threadIdx.x;
    const int lane = t & 31;
    const int wrp  = t >> 5;

    const size_t base = ((size_t)b * NN + (size_t)g * RPB) * NN;
    const float2* M2  = reinterpret_cast<const float2*>(Min + base);

    // ---- Prologue: build scaled fp16 K tile in SMEM ----
    for (int idx = t; idx < RPB * NH; idx += NT) {
        float2 m = M2[idx];
        float k0 = KSCALE * __expf(-10.0f * fminf(m.x, 5.0f));
        float k1 = KSCALE * __expf(-10.0f * fminf(m.y, 5.0f));
        Ks[idx] = __floats2half2_rn(k0, k1);
    }
    if (t < RPB) u_s[t] = RINV;
    __syncthreads();

    unsigned* ctr = &g_bar[b][0];

    for (int it = 0; it <= ITERS; ++it) {
        const int buf = it & 1;

        // ---- Phase A: thread t owns cols [2t, 2t+1]; sum over my 64 rows ----
        float a0 = 0.f, a1 = 0.f;
        {
            const float4* u4 = reinterpret_cast<const float4*>(u_s);
            #pragma unroll
            for (int r4 = 0; r4 < 16; ++r4) {
                float4 u = u4[r4];
                float2 f;
                f = __half22float2(Ks[(r4*4+0)*NH + t]); a0 = fmaf(f.x,u.x,a0); a1 = fmaf(f.y,u.x,a1);
                f = __half22float2(Ks[(r4*4+1)*NH + t]); a0 = fmaf(f.x,u.y,a0); a1 = fmaf(f.y,u.y,a1);
                f = __half22float2(Ks[(r4*4+2)*NH + t]); a0 = fmaf(f.x,u.z,a0); a1 = fmaf(f.y,u.z,a1);
                f = __half22float2(Ks[(r4*4+3)*NH + t]); a0 = fmaf(f.x,u.w,a0); a1 = fmaf(f.y,u.w,a1);
            }
        }
        __stcg(&g_wp[buf][b][g][t], __floats2half2_rn(a0, a1));

        // ---- Single per-batch barrier ----
        __syncthreads();
        if (t == 0) {
            red_rel_add1(ctr);
            const unsigned target = (unsigned)(it + 1) * GG;
            while (ld_acq(ctr) < target) { }
        }
        __syncthreads();

        // ---- Every block reduces all 16 partials for its 2 columns -> v ----
        {
            float w0 = 0.f, w1 = 0.f;
            #pragma unroll
            for (int p = 0; p < GG; ++p) {
                float2 f = __half22float2(__ldcg(&g_wp[buf][b][p][t]));
                w0 += f.x; w1 += f.y;
            }
            float2 vv;
            vv.x = __fdividef(RINV, w0);   // = v_true / KSCALE
            vv.y = __fdividef(RINV, w1);
            reinterpret_cast<float2*>(v_s)[t] = vv;
        }
        __syncthreads();

        if (it < ITERS) {
            // ---- Phase B: warp wrp handles rows [4*wrp, 4*wrp+4) ----
            float4 vr[8];
            #pragma unroll
            for (int q = 0; q < 8; ++q)
                vr[q] = reinterpret_cast<const float4*>(v_s)[lane + 32*q];

            #pragma unroll
            for (int k = 0; k < 4; ++k) {
                const int r = wrp * 4 + k;
                const uint2* row = reinterpret_cast<const uint2*>(Ks + (size_t)r * NH);
                float s = 0.f;
                #pragma unroll
                for (int q = 0; q < 8; ++q) {
                    uint2 pk = row[lane + 32*q];
                    float2 f0 = __half22float2(*reinterpret_cast<__half2*>(&pk.x));
                    float2 f1 = __half22float2(*reinterpret_cast<__half2*>(&pk.y));
                    s = fmaf(f0.x, vr[q].x, s);
                    s = fmaf(f0.y, vr[q].y, s);
                    s = fmaf(f1.x, vr[q].z, s);
                    s = fmaf(f1.y, vr[q].w, s);
                }
                #pragma unroll
                for (int off = 16; off; off >>= 1)
                    s += __shfl_xor_sync(0xffffffffu, s, off);
                if (lane == 0) u_s[r] = __fdividef(RINV, s);
            }
            __syncthreads();
        }
    }

    // ---- Epilogue: P = u * exp(-10*min(M,5)) * (KSCALE * v_s), fp32 K ----
    {
        float2* out2 = reinterpret_cast<float2*>(out + base);
        const float v0 = KSCALE * v_s[2*t + 0];
        const float v1 = KSCALE * v_s[2*t + 1];
        #pragma unroll 4
        for (int r = 0; r < RPB; ++r) {
            float ur = u_s[r];
            float2 m = M2[r * NH + t];
            float2 o;
            o.x = ur * __expf(-10.0f * fminf(m.x, 5.0f)) * v0;
            o.y = ur * __expf(-10.0f * fminf(m.y, 5.0f)) * v1;
            out2[r * NH + t] = o;
        }
    }
}

extern "C" void kernel_launch(void* const* d_in, const int* in_sizes, int n_in,
                              void* d_out, int out_size) {
    (void)in_sizes; (void)n_in; (void)out_size;
    const float* M = (const float*)d_in[0];
    float* out = (float*)d_out;

    cudaFuncSetAttribute(sinkhorn_persistent,
                         cudaFuncAttributeMaxDynamicSharedMemorySize, SMEM_BYTES);

    zero_bar_kernel<<<1, 32>>>();
    sinkhorn_persistent<<<BB * GG, NT, SMEM_BYTES>>>(M, out);
}